// round 1
// baseline (speedup 1.0000x reference)
#include <cuda_runtime.h>

#define N_NODES 50000
#define N_EDGES 800000
#define N_GRAPHS 50
#define IN_FEATS 128
#define H1F 64
#define O2F 32

// ---------------- scratch (device globals; no allocation allowed) ----------
__device__ float    g_z1[N_NODES * H1F];
__device__ float    g_agg1[N_NODES * H1F];   // becomes h1 in place
__device__ float    g_z2[N_NODES * O2F];
__device__ float    g_agg2[N_NODES * O2F];   // becomes h2 in place
__device__ float    g_el[N_NODES];
__device__ float    g_er[N_NODES];
__device__ unsigned g_m[N_NODES];            // ordered-uint encoded float max
__device__ float    g_s[N_NODES];
__device__ float    g_p[N_EDGES];            // logit, then p = exp(logit - m)
__device__ float    g_cnt[N_GRAPHS];

// ------------- order-preserving float<->uint map for atomicMax -------------
__device__ __forceinline__ unsigned f2ord(float f) {
    unsigned u = __float_as_uint(f);
    return (u & 0x80000000u) ? ~u : (u | 0x80000000u);
}
__device__ __forceinline__ float ord2f(unsigned u) {
    return __uint_as_float((u & 0x80000000u) ? (u & 0x7FFFFFFFu) : ~u);
}

// ---------------- init kernels ----------------------------------------------
__global__ void init_nodes_kernel() {
    int i = blockIdx.x * blockDim.x + threadIdx.x;
    if (i < N_NODES) {
        g_m[i] = 0x007FFFFFu;   // ord(-inf)
        g_s[i] = 0.0f;
    }
}

__global__ void zero_kernel(float* __restrict__ p, int n) {
    int i = blockIdx.x * blockDim.x + threadIdx.x;
    int stride = gridDim.x * blockDim.x;
    for (; i < n; i += stride) p[i] = 0.0f;
}

// ---------------- node GEMM + attention logits ------------------------------
// blockDim = NB*OUT (=256). NB nodes per block. Computes Z = H @ W and
// el = Z@al, er = Z@ar via in-block segmented reduction.
template <int IN, int OUT, int NB>
__global__ void gemm_attn_kernel(const float* __restrict__ H,
                                 const float* __restrict__ W,
                                 const float* __restrict__ al,
                                 const float* __restrict__ ar,
                                 float* __restrict__ Z) {
    __shared__ float shx[NB * IN];
    __shared__ float sl[NB * OUT];
    __shared__ float sr[NB * OUT];

    int base = blockIdx.x * NB;
    for (int t = threadIdx.x; t < NB * IN; t += NB * OUT) {
        int node = base + t / IN;
        shx[t] = (node < N_NODES) ? H[(size_t)node * IN + (t % IN)] : 0.0f;
    }
    __syncthreads();

    int local = threadIdx.x / OUT;
    int j     = threadIdx.x % OUT;
    int node  = base + local;

    float acc = 0.0f;
#pragma unroll 8
    for (int k = 0; k < IN; k++)
        acc += shx[local * IN + k] * W[k * OUT + j];

    if (node < N_NODES) Z[(size_t)node * OUT + j] = acc;

    sl[threadIdx.x] = acc * al[j];
    sr[threadIdx.x] = acc * ar[j];
    __syncthreads();
#pragma unroll
    for (int off = OUT / 2; off > 0; off >>= 1) {
        if (j < off) {
            sl[threadIdx.x] += sl[threadIdx.x + off];
            sr[threadIdx.x] += sr[threadIdx.x + off];
        }
        __syncthreads();
    }
    if (j == 0 && node < N_NODES) {
        g_el[node] = sl[threadIdx.x];
        g_er[node] = sr[threadIdx.x];
    }
}

// ---------------- edge passes ------------------------------------------------
__global__ void edge_logit_kernel(const int* __restrict__ src,
                                  const int* __restrict__ dst) {
    int i = blockIdx.x * blockDim.x + threadIdx.x;
    if (i >= N_EDGES) return;
    int sN = src[i], dN = dst[i];
    float v = g_el[sN] + g_er[dN];
    v = (v > 0.0f) ? v : 0.2f * v;   // GAT_SLOPE
    g_p[i] = v;
    atomicMax(&g_m[dN], f2ord(v));
}

__global__ void edge_exp_kernel(const int* __restrict__ dst) {
    int i = blockIdx.x * blockDim.x + threadIdx.x;
    if (i >= N_EDGES) return;
    int dN = dst[i];
    float m = ord2f(g_m[dN]);
    float p = expf(g_p[i] - m);
    g_p[i] = p;
    atomicAdd(&g_s[dN], p);
}

// one warp per edge; lanes < OUT/4 each move a float4
template <int OUT>
__global__ void edge_agg_kernel(const int* __restrict__ src,
                                const int* __restrict__ dst,
                                const float* __restrict__ Z,
                                float* __restrict__ AGG) {
    int i    = (blockIdx.x * blockDim.x + threadIdx.x) >> 5;
    int lane = threadIdx.x & 31;
    if (i >= N_EDGES) return;
    int dN = dst[i];
    float alpha = g_p[i] / g_s[dN];
    if (lane < OUT / 4) {
        int sN = src[i];
        float4 v = ((const float4*)(Z + (size_t)sN * OUT))[lane];
        v.x *= alpha; v.y *= alpha; v.z *= alpha; v.w *= alpha;
        atomicAdd(((float4*)(AGG + (size_t)dN * OUT)) + lane, v);
    }
}

// ---------------- bias + leaky_relu(0.01), in place --------------------------
template <int OUT>
__global__ void bias_act_kernel(float* __restrict__ A,
                                const float* __restrict__ b) {
    int i = blockIdx.x * blockDim.x + threadIdx.x;
    if (i >= N_NODES * OUT) return;
    float v = A[i] + b[i % OUT];
    A[i] = (v > 0.0f) ? v : 0.01f * v;
}

// ---------------- pooling ----------------------------------------------------
__global__ void pool_zero_kernel(float* __restrict__ out) {
    int i = blockIdx.x * blockDim.x + threadIdx.x;
    if (i < N_GRAPHS * O2F) out[i] = 0.0f;
    if (i < N_GRAPHS) g_cnt[i] = 0.0f;
}

__global__ void pool_acc_kernel(const int* __restrict__ gid,
                                const float* __restrict__ h,
                                float* __restrict__ out) {
    int i = blockIdx.x * blockDim.x + threadIdx.x;
    if (i >= N_NODES * O2F) return;
    int node = i / O2F, c = i % O2F;
    int g = gid[node];
    atomicAdd(&out[g * O2F + c], h[i]);
    if (c == 0) atomicAdd(&g_cnt[g], 1.0f);
}

__global__ void pool_div_kernel(float* __restrict__ out) {
    int i = blockIdx.x * blockDim.x + threadIdx.x;
    if (i >= N_GRAPHS * O2F) return;
    float c = g_cnt[i / O2F];
    out[i] /= fmaxf(c, 1.0f);
}

// ---------------- host launch -------------------------------------------------
extern "C" void kernel_launch(void* const* d_in, const int* in_sizes, int n_in,
                              void* d_out, int out_size) {
    const float* x   = (const float*)d_in[0];
    const int*   src = (const int*)d_in[1];
    const int*   dst = (const int*)d_in[2];
    const int*   gid = (const int*)d_in[3];
    const float* W1  = (const float*)d_in[4];
    const float* al1 = (const float*)d_in[5];
    const float* ar1 = (const float*)d_in[6];
    const float* b1  = (const float*)d_in[7];
    const float* W2  = (const float*)d_in[8];
    const float* al2 = (const float*)d_in[9];
    const float* ar2 = (const float*)d_in[10];
    const float* b2  = (const float*)d_in[11];
    float* out = (float*)d_out;

    float *z1, *agg1, *z2, *agg2;
    cudaGetSymbolAddress((void**)&z1,   g_z1);
    cudaGetSymbolAddress((void**)&agg1, g_agg1);
    cudaGetSymbolAddress((void**)&z2,   g_z2);
    cudaGetSymbolAddress((void**)&agg2, g_agg2);

    const int TB = 256;
    int edge_blocks  = (N_EDGES + TB - 1) / TB;
    int wedge_blocks = (N_EDGES * 32 + TB - 1) / TB;   // warp per edge
    int node_blocks  = (N_NODES + TB - 1) / TB;

    // ---------------- layer 1 ----------------
    init_nodes_kernel<<<node_blocks, TB>>>();
    zero_kernel<<<2048, TB>>>(agg1, N_NODES * H1F);
    gemm_attn_kernel<IN_FEATS, H1F, 4><<<N_NODES / 4, 256>>>(x, W1, al1, ar1, z1);
    edge_logit_kernel<<<edge_blocks, TB>>>(src, dst);
    edge_exp_kernel<<<edge_blocks, TB>>>(dst);
    edge_agg_kernel<H1F><<<wedge_blocks, TB>>>(src, dst, z1, agg1);
    bias_act_kernel<H1F><<<(N_NODES * H1F + TB - 1) / TB, TB>>>(agg1, b1);

    // ---------------- layer 2 ----------------
    init_nodes_kernel<<<node_blocks, TB>>>();
    zero_kernel<<<2048, TB>>>(agg2, N_NODES * O2F);
    gemm_attn_kernel<H1F, O2F, 8><<<N_NODES / 8, 256>>>(agg1, W2, al2, ar2, z2);
    edge_logit_kernel<<<edge_blocks, TB>>>(src, dst);
    edge_exp_kernel<<<edge_blocks, TB>>>(dst);
    edge_agg_kernel<O2F><<<wedge_blocks, TB>>>(src, dst, z2, agg2);
    bias_act_kernel<O2F><<<(N_NODES * O2F + TB - 1) / TB, TB>>>(agg2, b2);

    // ---------------- pooling ----------------
    pool_zero_kernel<<<(N_GRAPHS * O2F + TB - 1) / TB, TB>>>(out);
    pool_acc_kernel<<<(N_NODES * O2F + TB - 1) / TB, TB>>>(gid, agg2, out);
    pool_div_kernel<<<(N_GRAPHS * O2F + TB - 1) / TB, TB>>>(out);
}

// round 2
// speedup vs baseline: 1.9920x; 1.9920x over previous
#include <cuda_runtime.h>

#define N_NODES 50000
#define N_EDGES 800000
#define N_GRAPHS 50
#define IN_FEATS 128
#define H1F 64
#define O2F 32
#define NEG_INF (-1e30f)

// ---------------- scratch (device globals; no allocation allowed) ----------
__device__ float g_z1[N_NODES * H1F];
__device__ float g_h1[N_NODES * H1F];
__device__ float g_z2[N_NODES * O2F];
__device__ float g_el[N_NODES];
__device__ float g_er[N_NODES];
__device__ int   g_deg[N_NODES];
__device__ int   g_row[N_NODES + 1];
__device__ int   g_cur[N_NODES];
__device__ int   g_esrc[N_EDGES];    // src node per dst-sorted slot
__device__ int   g_bsum[64];
__device__ float g_cnt[N_GRAPHS];

// ---------------- init: zero degree histogram, output, counts ---------------
__global__ void init_kernel(float* __restrict__ out) {
    int i = blockIdx.x * blockDim.x + threadIdx.x;
    if (i < N_NODES) g_deg[i] = 0;
    if (i < N_GRAPHS * O2F) out[i] = 0.0f;
    if (i < N_GRAPHS) g_cnt[i] = 0.0f;
}

// ---------------- CSR build --------------------------------------------------
__global__ void hist_kernel(const int* __restrict__ dst) {
    int i = blockIdx.x * blockDim.x + threadIdx.x;
    if (i < N_EDGES) atomicAdd(&g_deg[dst[i]], 1);
}

// chunked inclusive scan (1024 per block) -> g_row[i+1], block totals -> g_bsum
__global__ void scan1_kernel() {
    __shared__ int sh[1024];
    int i = blockIdx.x * 1024 + threadIdx.x;
    int v = (i < N_NODES) ? g_deg[i] : 0;
    sh[threadIdx.x] = v;
    __syncthreads();
#pragma unroll
    for (int off = 1; off < 1024; off <<= 1) {
        int t = (threadIdx.x >= off) ? sh[threadIdx.x - off] : 0;
        __syncthreads();
        sh[threadIdx.x] += t;
        __syncthreads();
    }
    if (i < N_NODES) g_row[i + 1] = sh[threadIdx.x];
    if (threadIdx.x == 1023) g_bsum[blockIdx.x] = sh[1023];
}

__global__ void scan2_kernel(int nblocks) {
    if (threadIdx.x == 0 && blockIdx.x == 0) {
        int run = 0;
        for (int b = 0; b < nblocks; b++) {
            int t = g_bsum[b];
            g_bsum[b] = run;
            run += t;
        }
    }
}

__global__ void scan3_kernel() {
    int i = blockIdx.x * 1024 + threadIdx.x;
    if (i < N_NODES) {
        int incl = g_row[i + 1] + g_bsum[blockIdx.x];
        g_row[i + 1] = incl;
        g_cur[i] = incl - g_deg[i];       // exclusive = row start
        if (i == 0) g_row[0] = 0;
    }
}

__global__ void scatter_kernel(const int* __restrict__ src,
                               const int* __restrict__ dst) {
    int i = blockIdx.x * blockDim.x + threadIdx.x;
    if (i >= N_EDGES) return;
    int d = dst[i];
    int pos = atomicAdd(&g_cur[d], 1);
    g_esrc[pos] = src[i];
}

// ---------------- node GEMM + attention logits ------------------------------
// Block = NB nodes * (OUT/4) threads; each thread computes 4 outputs.
// W and the node tile live in smem; el/er via shfl reduction.
template <int IN, int OUT, int NB>
__global__ void gemm_attn_kernel(const float* __restrict__ H,
                                 const float* __restrict__ W,
                                 const float* __restrict__ al,
                                 const float* __restrict__ ar,
                                 float* __restrict__ Z) {
    constexpr int JT  = 4;
    constexpr int TPN = OUT / JT;
    constexpr int NT  = NB * TPN;
    __shared__ float sW[IN * OUT];
    __shared__ float sx[NB * IN];

    int tid = threadIdx.x;
    for (int t = tid; t < IN * OUT / 4; t += NT)
        ((float4*)sW)[t] = ((const float4*)W)[t];

    int base = blockIdx.x * NB;
    for (int t = tid; t < NB * IN / 4; t += NT) {
        int node = base + t / (IN / 4);
        ((float4*)sx)[t] = (node < N_NODES)
            ? ((const float4*)H)[(size_t)node * (IN / 4) + (t % (IN / 4))]
            : make_float4(0.f, 0.f, 0.f, 0.f);
    }
    __syncthreads();

    int nl = tid / TPN;
    int jg = tid % TPN;
    int node = base + nl;

    float acc0 = 0.f, acc1 = 0.f, acc2 = 0.f, acc3 = 0.f;
    const float4* xv = (const float4*)(sx + nl * IN);
#pragma unroll 8
    for (int k4 = 0; k4 < IN / 4; k4++) {
        float4 xq = xv[k4];
        float xs[4] = {xq.x, xq.y, xq.z, xq.w};
#pragma unroll
        for (int u = 0; u < 4; u++) {
            float4 wq = *(const float4*)(sW + (k4 * 4 + u) * OUT + jg * JT);
            acc0 += xs[u] * wq.x;
            acc1 += xs[u] * wq.y;
            acc2 += xs[u] * wq.z;
            acc3 += xs[u] * wq.w;
        }
    }

    float l = acc0 * al[jg * JT] + acc1 * al[jg * JT + 1] +
              acc2 * al[jg * JT + 2] + acc3 * al[jg * JT + 3];
    float r = acc0 * ar[jg * JT] + acc1 * ar[jg * JT + 1] +
              acc2 * ar[jg * JT + 2] + acc3 * ar[jg * JT + 3];
#pragma unroll
    for (int off = TPN / 2; off > 0; off >>= 1) {
        l += __shfl_xor_sync(0xffffffffu, l, off);
        r += __shfl_xor_sync(0xffffffffu, r, off);
    }

    if (node < N_NODES) {
        *(float4*)(Z + (size_t)node * OUT + jg * JT) =
            make_float4(acc0, acc1, acc2, acc3);
        if (jg == 0) {
            g_el[node] = l;
            g_er[node] = r;
        }
    }
}

// ---------------- fused softmax + aggregation, one warp per dst node --------
// Online softmax with rescaled register accumulators; single pass over edges.
template <int OUT, bool POOL>
__global__ void node_agg_kernel(const float* __restrict__ Z,
                                const float* __restrict__ b,
                                float* __restrict__ Hout,
                                const int* __restrict__ gid,
                                float* __restrict__ pool_out) {
    int wid  = (blockIdx.x * blockDim.x + threadIdx.x) >> 5;
    int lane = threadIdx.x & 31;
    if (wid >= N_NODES) return;

    int rs = g_row[wid], re = g_row[wid + 1];
    float erd = g_er[wid];

    float m = NEG_INF, s = 0.f;
    float acc0 = 0.f, acc1 = 0.f;

    for (int base = rs; base < re; base += 32) {
        int t = base + lane;
        bool valid = t < re;
        int sN = valid ? g_esrc[t] : 0;
        float e = NEG_INF;
        if (valid) {
            float v = g_el[sN] + erd;
            e = (v > 0.f) ? v : 0.2f * v;
        }
        float cm = e;
#pragma unroll
        for (int off = 16; off > 0; off >>= 1)
            cm = fmaxf(cm, __shfl_xor_sync(0xffffffffu, cm, off));
        float mnew = fmaxf(m, cm);
        float scale = __expf(m - mnew);
        s *= scale; acc0 *= scale; acc1 *= scale;

        float a = valid ? __expf(e - mnew) : 0.f;
        float as = a;
#pragma unroll
        for (int off = 16; off > 0; off >>= 1)
            as += __shfl_xor_sync(0xffffffffu, as, off);
        s += as;
        m = mnew;

        int cnt = min(32, re - base);
#pragma unroll 4
        for (int j = 0; j < cnt; j++) {
            float alpha = __shfl_sync(0xffffffffu, a, j);
            int   sn    = __shfl_sync(0xffffffffu, sN, j);
            if (OUT == 64) {
                float2 zv = ((const float2*)(Z + (size_t)sn * 64))[lane];
                acc0 += alpha * zv.x;
                acc1 += alpha * zv.y;
            } else {
                float zv = Z[(size_t)sn * 32 + lane];
                acc0 += alpha * zv;
            }
        }
    }

    float inv_s = (re > rs) ? 1.f / s : 0.f;
    if (OUT == 64) {
        float h0 = acc0 * inv_s + b[2 * lane];
        float h1 = acc1 * inv_s + b[2 * lane + 1];
        h0 = (h0 > 0.f) ? h0 : 0.01f * h0;
        h1 = (h1 > 0.f) ? h1 : 0.01f * h1;
        ((float2*)(Hout + (size_t)wid * 64))[lane] = make_float2(h0, h1);
    } else {
        float h = acc0 * inv_s + b[lane];
        h = (h > 0.f) ? h : 0.01f * h;
        if (POOL) {
            int g = gid[wid];
            atomicAdd(&pool_out[g * O2F + lane], h);
            if (lane == 0) atomicAdd(&g_cnt[g], 1.f);
        } else {
            Hout[(size_t)wid * 32 + lane] = h;
        }
    }
}

// ---------------- final divide ----------------------------------------------
__global__ void pool_div_kernel(float* __restrict__ out) {
    int i = blockIdx.x * blockDim.x + threadIdx.x;
    if (i >= N_GRAPHS * O2F) return;
    float c = g_cnt[i / O2F];
    out[i] /= fmaxf(c, 1.0f);
}

// ---------------- host launch -------------------------------------------------
extern "C" void kernel_launch(void* const* d_in, const int* in_sizes, int n_in,
                              void* d_out, int out_size) {
    const float* x   = (const float*)d_in[0];
    const int*   src = (const int*)d_in[1];
    const int*   dst = (const int*)d_in[2];
    const int*   gid = (const int*)d_in[3];
    const float* W1  = (const float*)d_in[4];
    const float* al1 = (const float*)d_in[5];
    const float* ar1 = (const float*)d_in[6];
    const float* b1  = (const float*)d_in[7];
    const float* W2  = (const float*)d_in[8];
    const float* al2 = (const float*)d_in[9];
    const float* ar2 = (const float*)d_in[10];
    const float* b2  = (const float*)d_in[11];
    float* out = (float*)d_out;

    float *z1, *h1, *z2;
    cudaGetSymbolAddress((void**)&z1, g_z1);
    cudaGetSymbolAddress((void**)&h1, g_h1);
    cudaGetSymbolAddress((void**)&z2, g_z2);

    const int TB = 256;
    const int edge_blocks = (N_EDGES + TB - 1) / TB;
    const int scan_blocks = (N_NODES + 1023) / 1024;   // 49
    const int node_warp_blocks = (N_NODES * 32 + TB - 1) / TB;  // warp/node

    // CSR build (shared by both layers)
    init_kernel<<<(N_NODES + TB - 1) / TB, TB>>>(out);
    hist_kernel<<<edge_blocks, TB>>>(dst);
    scan1_kernel<<<scan_blocks, 1024>>>();
    scan2_kernel<<<1, 32>>>(scan_blocks);
    scan3_kernel<<<scan_blocks, 1024>>>();
    scatter_kernel<<<edge_blocks, TB>>>(src, dst);

    // layer 1: 16 nodes/block * 16 threads/node = 256
    gemm_attn_kernel<IN_FEATS, H1F, 16><<<(N_NODES + 15) / 16, 256>>>(
        x, W1, al1, ar1, z1);
    node_agg_kernel<H1F, false><<<node_warp_blocks, TB>>>(
        z1, b1, h1, gid, out);

    // layer 2: 32 nodes/block * 8 threads/node = 256
    gemm_attn_kernel<H1F, O2F, 32><<<(N_NODES + 31) / 32, 256>>>(
        h1, W2, al2, ar2, z2);
    node_agg_kernel<O2F, true><<<node_warp_blocks, TB>>>(
        z2, b2, nullptr, gid, out);

    pool_div_kernel<<<(N_GRAPHS * O2F + TB - 1) / TB, TB>>>(out);
}

// round 3
// speedup vs baseline: 2.0879x; 1.0481x over previous
#include <cuda_runtime.h>

#define N_NODES 50000
#define N_EDGES 800000
#define N_GRAPHS 50
#define IN_FEATS 128
#define H1F 64
#define O2F 32
#define NEG_INF (-1e30f)

// ---------------- scratch (device globals; no allocation allowed) ----------
__device__ float g_z1[N_NODES * H1F];
__device__ float g_h1[N_NODES * H1F];
__device__ float g_z2[N_NODES * O2F];
__device__ float g_el[N_NODES];
__device__ float g_er[N_NODES];
__device__ int   g_deg[N_NODES];
__device__ int   g_row[N_NODES + 1];
__device__ int   g_cur[N_NODES];
__device__ int   g_esrc[N_EDGES];    // src node per dst-sorted slot
__device__ int   g_bsum[64];
__device__ float g_cnt[N_GRAPHS];

// ---------------- init: zero degree histogram, output, counts ---------------
__global__ void init_kernel(float* __restrict__ out) {
    int i = blockIdx.x * blockDim.x + threadIdx.x;
    if (i < N_NODES) g_deg[i] = 0;
    if (i < N_GRAPHS * O2F) out[i] = 0.0f;
    if (i < N_GRAPHS) g_cnt[i] = 0.0f;
}

// ---------------- CSR build --------------------------------------------------
__global__ void hist_kernel(const int* __restrict__ dst) {
    int i = blockIdx.x * blockDim.x + threadIdx.x;
    if (i < N_EDGES) atomicAdd(&g_deg[dst[i]], 1);
}

// chunked inclusive scan (1024 per block) -> g_row[i+1], block totals -> g_bsum
__global__ void scan1_kernel() {
    __shared__ int sh[1024];
    int i = blockIdx.x * 1024 + threadIdx.x;
    int v = (i < N_NODES) ? g_deg[i] : 0;
    sh[threadIdx.x] = v;
    __syncthreads();
#pragma unroll
    for (int off = 1; off < 1024; off <<= 1) {
        int t = (threadIdx.x >= off) ? sh[threadIdx.x - off] : 0;
        __syncthreads();
        sh[threadIdx.x] += t;
        __syncthreads();
    }
    if (i < N_NODES) g_row[i + 1] = sh[threadIdx.x];
    if (threadIdx.x == 1023) g_bsum[blockIdx.x] = sh[1023];
}

// parallel warp-scan over block sums (exclusive, in place)
__global__ void scan2_kernel(int nblocks) {
    int lane = threadIdx.x;
    int carry = 0;
    for (int base = 0; base < nblocks; base += 32) {
        int idx = base + lane;
        int orig = (idx < nblocks) ? g_bsum[idx] : 0;
        int v = orig;
#pragma unroll
        for (int off = 1; off < 32; off <<= 1) {
            int t = __shfl_up_sync(0xffffffffu, v, off);
            if (lane >= off) v += t;
        }
        if (idx < nblocks) g_bsum[idx] = carry + v - orig;  // exclusive
        carry += __shfl_sync(0xffffffffu, v, 31);
    }
}

__global__ void scan3_kernel() {
    int i = blockIdx.x * 1024 + threadIdx.x;
    if (i < N_NODES) {
        int incl = g_row[i + 1] + g_bsum[blockIdx.x];
        g_row[i + 1] = incl;
        g_cur[i] = incl - g_deg[i];       // exclusive = row start
        if (i == 0) g_row[0] = 0;
    }
}

__global__ void scatter_kernel(const int* __restrict__ src,
                               const int* __restrict__ dst) {
    int i = blockIdx.x * blockDim.x + threadIdx.x;
    if (i >= N_EDGES) return;
    int d = dst[i];
    int pos = atomicAdd(&g_cur[d], 1);
    g_esrc[pos] = src[i];
}

// ---------------- node GEMM + attention logits ------------------------------
template <int IN, int OUT, int NB>
__global__ void gemm_attn_kernel(const float* __restrict__ H,
                                 const float* __restrict__ W,
                                 const float* __restrict__ al,
                                 const float* __restrict__ ar,
                                 float* __restrict__ Z) {
    constexpr int JT  = 4;
    constexpr int TPN = OUT / JT;
    constexpr int NT  = NB * TPN;
    __shared__ float sW[IN * OUT];
    __shared__ float sx[NB * IN];

    int tid = threadIdx.x;
    for (int t = tid; t < IN * OUT / 4; t += NT)
        ((float4*)sW)[t] = ((const float4*)W)[t];

    int base = blockIdx.x * NB;
    for (int t = tid; t < NB * IN / 4; t += NT) {
        int node = base + t / (IN / 4);
        ((float4*)sx)[t] = (node < N_NODES)
            ? ((const float4*)H)[(size_t)node * (IN / 4) + (t % (IN / 4))]
            : make_float4(0.f, 0.f, 0.f, 0.f);
    }
    __syncthreads();

    int nl = tid / TPN;
    int jg = tid % TPN;
    int node = base + nl;

    float acc0 = 0.f, acc1 = 0.f, acc2 = 0.f, acc3 = 0.f;
    const float4* xv = (const float4*)(sx + nl * IN);
#pragma unroll 8
    for (int k4 = 0; k4 < IN / 4; k4++) {
        float4 xq = xv[k4];
        float xs[4] = {xq.x, xq.y, xq.z, xq.w};
#pragma unroll
        for (int u = 0; u < 4; u++) {
            float4 wq = *(const float4*)(sW + (k4 * 4 + u) * OUT + jg * JT);
            acc0 += xs[u] * wq.x;
            acc1 += xs[u] * wq.y;
            acc2 += xs[u] * wq.z;
            acc3 += xs[u] * wq.w;
        }
    }

    float l = acc0 * al[jg * JT] + acc1 * al[jg * JT + 1] +
              acc2 * al[jg * JT + 2] + acc3 * al[jg * JT + 3];
    float r = acc0 * ar[jg * JT] + acc1 * ar[jg * JT + 1] +
              acc2 * ar[jg * JT + 2] + acc3 * ar[jg * JT + 3];
#pragma unroll
    for (int off = TPN / 2; off > 0; off >>= 1) {
        l += __shfl_xor_sync(0xffffffffu, l, off);
        r += __shfl_xor_sync(0xffffffffu, r, off);
    }

    if (node < N_NODES) {
        *(float4*)(Z + (size_t)node * OUT + jg * JT) =
            make_float4(acc0, acc1, acc2, acc3);
        if (jg == 0) {
            g_el[node] = l;
            g_er[node] = r;
        }
    }
}

// ---------------- fused softmax + aggregation, one warp per dst node --------
// Online softmax; inner loop processes EPI edges in parallel with float4
// gathers (OUT/4 lanes per edge).
template <int OUT, bool POOL>
__global__ void node_agg_kernel(const float* __restrict__ Z,
                                const float* __restrict__ b,
                                float* __restrict__ Hout,
                                const int* __restrict__ gid,
                                float* __restrict__ pool_out) {
    constexpr int LPE = OUT / 4;       // lanes per edge
    constexpr int EPI = 32 / LPE;      // edges per inner iteration
    int wid  = (blockIdx.x * blockDim.x + threadIdx.x) >> 5;
    int lane = threadIdx.x & 31;
    if (wid >= N_NODES) return;

    int rs = g_row[wid], re = g_row[wid + 1];
    float erd = g_er[wid];
    int sub = lane / LPE;              // which edge of the group this lane serves
    int fl  = lane % LPE;              // feature quad index

    float m = NEG_INF, s = 0.f;
    float4 acc = make_float4(0.f, 0.f, 0.f, 0.f);

    for (int base = rs; base < re; base += 32) {
        int t = base + lane;
        bool valid = t < re;
        int sN = valid ? g_esrc[t] : 0;
        float e = NEG_INF;
        if (valid) {
            float v = g_el[sN] + erd;
            e = (v > 0.f) ? v : 0.2f * v;
        }
        float cm = e;
#pragma unroll
        for (int off = 16; off > 0; off >>= 1)
            cm = fmaxf(cm, __shfl_xor_sync(0xffffffffu, cm, off));
        float mnew = fmaxf(m, cm);
        float scale = __expf(m - mnew);
        s *= scale;
        acc.x *= scale; acc.y *= scale; acc.z *= scale; acc.w *= scale;

        float a = valid ? __expf(e - mnew) : 0.f;   // a == 0 for invalid lanes
        float as = a;
#pragma unroll
        for (int off = 16; off > 0; off >>= 1)
            as += __shfl_xor_sync(0xffffffffu, as, off);
        s += as;
        m = mnew;

        int cnt = min(32, re - base);
        // a==0 and sN==0 for lanes >= cnt, so no per-edge guards needed
        for (int j = 0; j < cnt; j += EPI) {
            int ei = j + sub;
            float alpha = __shfl_sync(0xffffffffu, a, ei);
            int   sn    = __shfl_sync(0xffffffffu, sN, ei);
            float4 zv = ((const float4*)(Z + (size_t)sn * OUT))[fl];
            acc.x += alpha * zv.x;
            acc.y += alpha * zv.y;
            acc.z += alpha * zv.z;
            acc.w += alpha * zv.w;
        }
    }

    // fold the EPI partial accumulators down to lanes [0, LPE)
#pragma unroll
    for (int off = 16; off >= LPE; off >>= 1) {
        acc.x += __shfl_xor_sync(0xffffffffu, acc.x, off);
        acc.y += __shfl_xor_sync(0xffffffffu, acc.y, off);
        acc.z += __shfl_xor_sync(0xffffffffu, acc.z, off);
        acc.w += __shfl_xor_sync(0xffffffffu, acc.w, off);
    }

    if (lane < LPE) {
        float inv_s = (re > rs) ? 1.f / s : 0.f;
        float4 bq = ((const float4*)b)[fl];
        float4 h;
        h.x = acc.x * inv_s + bq.x;
        h.y = acc.y * inv_s + bq.y;
        h.z = acc.z * inv_s + bq.z;
        h.w = acc.w * inv_s + bq.w;
        h.x = (h.x > 0.f) ? h.x : 0.01f * h.x;
        h.y = (h.y > 0.f) ? h.y : 0.01f * h.y;
        h.z = (h.z > 0.f) ? h.z : 0.01f * h.z;
        h.w = (h.w > 0.f) ? h.w : 0.01f * h.w;
        if (POOL) {
            int g = gid[wid];
            atomicAdd(((float4*)(pool_out + g * O2F)) + fl, h);
            if (lane == 0) atomicAdd(&g_cnt[g], 1.f);
        } else {
            ((float4*)(Hout + (size_t)wid * OUT))[fl] = h;
        }
    }
}

// ---------------- final divide ----------------------------------------------
__global__ void pool_div_kernel(float* __restrict__ out) {
    int i = blockIdx.x * blockDim.x + threadIdx.x;
    if (i >= N_GRAPHS * O2F) return;
    float c = g_cnt[i / O2F];
    out[i] /= fmaxf(c, 1.0f);
}

// ---------------- stream/event singletons (created once, outside capture) ---
static cudaStream_t g_s1;
static cudaEvent_t  g_evFork, g_evJoin;
static int g_res_init = []() {
    cudaStreamCreateWithFlags(&g_s1, cudaStreamNonBlocking);
    cudaEventCreateWithFlags(&g_evFork, cudaEventDisableTiming);
    cudaEventCreateWithFlags(&g_evJoin, cudaEventDisableTiming);
    return 0;
}();

// ---------------- host launch -------------------------------------------------
extern "C" void kernel_launch(void* const* d_in, const int* in_sizes, int n_in,
                              void* d_out, int out_size) {
    const float* x   = (const float*)d_in[0];
    const int*   src = (const int*)d_in[1];
    const int*   dst = (const int*)d_in[2];
    const int*   gid = (const int*)d_in[3];
    const float* W1  = (const float*)d_in[4];
    const float* al1 = (const float*)d_in[5];
    const float* ar1 = (const float*)d_in[6];
    const float* b1  = (const float*)d_in[7];
    const float* W2  = (const float*)d_in[8];
    const float* al2 = (const float*)d_in[9];
    const float* ar2 = (const float*)d_in[10];
    const float* b2  = (const float*)d_in[11];
    float* out = (float*)d_out;

    float *z1, *h1, *z2;
    cudaGetSymbolAddress((void**)&z1, g_z1);
    cudaGetSymbolAddress((void**)&h1, g_h1);
    cudaGetSymbolAddress((void**)&z2, g_z2);

    const int TB = 256;
    const int edge_blocks = (N_EDGES + TB - 1) / TB;
    const int scan_blocks = (N_NODES + 1023) / 1024;   // 49
    const int node_warp_blocks = (N_NODES * 32 + TB - 1) / TB;  // warp/node

    // fork: CSR build + zeroing on side stream, gemm1 on main stream
    cudaEventRecord(g_evFork, 0);
    cudaStreamWaitEvent(g_s1, g_evFork, 0);

    init_kernel<<<(N_NODES + TB - 1) / TB, TB, 0, g_s1>>>(out);
    hist_kernel<<<edge_blocks, TB, 0, g_s1>>>(dst);
    scan1_kernel<<<scan_blocks, 1024, 0, g_s1>>>();
    scan2_kernel<<<1, 32, 0, g_s1>>>(scan_blocks);
    scan3_kernel<<<scan_blocks, 1024, 0, g_s1>>>();
    scatter_kernel<<<edge_blocks, TB, 0, g_s1>>>(src, dst);
    cudaEventRecord(g_evJoin, g_s1);

    // layer 1 GEMM overlaps CSR build
    gemm_attn_kernel<IN_FEATS, H1F, 16><<<(N_NODES + 15) / 16, 256>>>(
        x, W1, al1, ar1, z1);

    cudaStreamWaitEvent(0, g_evJoin, 0);   // join before aggregation

    node_agg_kernel<H1F, false><<<node_warp_blocks, TB>>>(
        z1, b1, h1, gid, out);

    // layer 2
    gemm_attn_kernel<H1F, O2F, 32><<<(N_NODES + 31) / 32, 256>>>(
        h1, W2, al2, ar2, z2);
    node_agg_kernel<O2F, true><<<node_warp_blocks, TB>>>(
        z2, b2, nullptr, gid, out);

    pool_div_kernel<<<(N_GRAPHS * O2F + TB - 1) / TB, TB>>>(out);
}